// round 17
// baseline (speedup 1.0000x reference)
#include <cuda_runtime.h>
#include <cuda_fp16.h>
#include <cstdint>
#include <cstddef>

#define D_MODEL 1024
#define N_HEADS 16
#define HEAD_DIM 64
#define BATCH 4
#define SEQ 2048
#define QKV_STRIDE (3 * D_MODEL)

// ------------------------------ scratch (fp16) -----------------------------
__device__ __half g_x16[(size_t)BATCH * SEQ * D_MODEL];
__device__ __half g_qkv16[(size_t)BATCH * SEQ * QKV_STRIDE];   // q cols pre-scaled 0.125*log2e
__device__ __half g_attn16[(size_t)BATCH * SEQ * D_MODEL];
__device__ __half g_wqkvT16[(size_t)3 * D_MODEL * D_MODEL];    // [3072][1024] k-major
__device__ __half g_woT16[(size_t)D_MODEL * D_MODEL];          // [1024][1024] k-major

// ------------------------------ helpers ------------------------------------
__device__ __forceinline__ uint32_t smem_u32(const void* p) {
    uint32_t a;
    asm("{ .reg .u64 t; cvta.to.shared.u64 t, %1; cvt.u32.u64 %0, t; }" : "=r"(a) : "l"(p));
    return a;
}
__device__ __forceinline__ uint32_t h2u(__half2 h) {
    return *reinterpret_cast<uint32_t*>(&h);
}
__device__ __forceinline__ uint32_t ex2_h2(uint32_t x) {
    uint32_t r; asm("ex2.approx.f16x2 %0, %1;" : "=r"(r) : "r"(x)); return r;
}
__device__ __forceinline__ void cp16(uint32_t dst, const void* src) {
    asm volatile("cp.async.ca.shared.global [%0], [%1], 16;" :: "r"(dst), "l"(src));
}
#define CP_COMMIT() asm volatile("cp.async.commit_group;" ::: "memory")
#define CP_WAIT0()  asm volatile("cp.async.wait_group 0;" ::: "memory")
#define CP_WAIT1()  asm volatile("cp.async.wait_group 1;" ::: "memory")

__device__ __forceinline__ void ldsm4(uint32_t* r, uint32_t addr) {
    asm volatile("ldmatrix.sync.aligned.m8n8.x4.shared.b16 {%0,%1,%2,%3}, [%4];"
        : "=r"(r[0]), "=r"(r[1]), "=r"(r[2]), "=r"(r[3]) : "r"(addr));
}
__device__ __forceinline__ void ldsm4t(uint32_t* r, uint32_t addr) {
    asm volatile("ldmatrix.sync.aligned.m8n8.x4.trans.shared.b16 {%0,%1,%2,%3}, [%4];"
        : "=r"(r[0]), "=r"(r[1]), "=r"(r[2]), "=r"(r[3]) : "r"(addr));
}
__device__ __forceinline__ void ldsm2t(uint32_t* r, uint32_t addr) {
    asm volatile("ldmatrix.sync.aligned.m8n8.x2.trans.shared.b16 {%0,%1}, [%2];"
        : "=r"(r[0]), "=r"(r[1]) : "r"(addr));
}

// D(f32) += A(f16) * B(f16) ; m16n8k16
__device__ __forceinline__ void mma16(float* c, const uint32_t* a, const uint32_t* b) {
    asm volatile(
        "mma.sync.aligned.m16n8k16.row.col.f32.f16.f16.f32 "
        "{%0,%1,%2,%3}, {%4,%5,%6,%7}, {%8,%9}, {%0,%1,%2,%3};"
        : "+f"(c[0]), "+f"(c[1]), "+f"(c[2]), "+f"(c[3])
        : "r"(a[0]), "r"(a[1]), "r"(a[2]), "r"(a[3]), "r"(b[0]), "r"(b[1]));
}

// ------------------------------ init kernels -------------------------------
__global__ void convert_x(const float* __restrict__ in, __half* __restrict__ out) {
    size_t i = ((size_t)blockIdx.x * blockDim.x + threadIdx.x) * 4;
    float4 v = *(const float4*)(in + i);
    *(__half2*)(out + i)     = __floats2half2_rn(v.x, v.y);
    *(__half2*)(out + i + 2) = __floats2half2_rn(v.z, v.w);
}

// out[C][R] = half(in[R][C])
__global__ void transpose_w(const float* __restrict__ in, __half* __restrict__ out,
                            int R, int C) {
    __shared__ float t[32][33];
    int c0 = blockIdx.x * 32, r0 = blockIdx.y * 32;
    #pragma unroll
    for (int j = 0; j < 4; j++) {
        int r = threadIdx.y + j * 8;
        t[r][threadIdx.x] = in[(size_t)(r0 + r) * C + c0 + threadIdx.x];
    }
    __syncthreads();
    #pragma unroll
    for (int j = 0; j < 4; j++) {
        int c = threadIdx.y + j * 8;
        out[(size_t)(c0 + c) * R + r0 + threadIdx.x] = __float2half_rn(t[threadIdx.x][c]);
    }
}

// ------------------------------ fp16 GEMM ----------------------------------
// C[M,N] = A[M,K] @ BT[N,K]^T + bias[N]. fp16 operands, fp32 accum.
// 128x128 CTA, BK=64, 3-stage cp.async, 256 thr / 8 warps, warp m32n64.
// Loader: 2 threads/row, each thread 32 halves = 64 bytes = 4 x cp16 at {0,16,32,48}.
#define GS_STR 72           // halves per row (144B)
#define G_STAGES 3
#define G_TILE (128 * GS_STR)
#define G_SMEM (G_STAGES * 2 * G_TILE * 2)    // 110,592 B
#define QSCALE (0.125f * 1.44269504088896f)   // fold softmax scale + log2e into Q

template<bool ROUND>
__global__ void __launch_bounds__(256, 2) gemm_mma(
    const __half* __restrict__ A, const __half* __restrict__ BT,
    const float* __restrict__ bias, void* __restrict__ Cv,
    int M, int N, int K, int qcols)
{
    extern __shared__ __half smh[];
    __half* As = smh;                       // [3][128][GS_STR]
    __half* Bs = smh + G_STAGES * G_TILE;   // [3][128][GS_STR]

    const int tid = threadIdx.x;
    const int lane = tid & 31, warp = tid >> 5;
    const int g = lane >> 2, q = lane & 3;
    const int wm = (warp >> 1) * 32, wn = (warp & 1) * 64;
    const int m0 = blockIdx.y * 128, n0 = blockIdx.x * 128;

    // loaders: 2 threads/row, each 32 contiguous halves (4 x cp16)
    const int lrow = tid >> 1, lch = (tid & 1) * 32;
    const __half* Ag = A + (size_t)(m0 + lrow) * K + lch;
    const __half* Bg = BT + (size_t)(n0 + lrow) * K + lch;
    const uint32_t asU = smem_u32(As), bsU = smem_u32(Bs);
    const uint32_t AsA = asU + (lrow * GS_STR + lch) * 2;
    const uint32_t BsA = bsU + (lrow * GS_STR + lch) * 2;

    const int a_r = (lane & 7) + ((lane >> 3) & 1) * 8;
    const int a_h = (lane >> 4) * 8;
    const int b_n = (lane & 7) + ((lane >> 4) & 1) * 8;
    const int b_h = ((lane >> 3) & 1) * 8;
    const uint32_t aoff = ((wm + a_r) * GS_STR + a_h) * 2;
    const uint32_t boff = ((wn + b_n) * GS_STR + b_h) * 2;

    float acc[2][8][4];
    #pragma unroll
    for (int i = 0; i < 2; i++)
        #pragma unroll
        for (int j = 0; j < 8; j++)
            #pragma unroll
            for (int t = 0; t < 4; t++) acc[i][j][t] = 0.0f;

    const int nk = K >> 6;    // BK = 64 halves

    #pragma unroll
    for (int s = 0; s < 2; s++) {
        uint32_t ad = AsA + s * G_TILE * 2;
        uint32_t bd = BsA + s * G_TILE * 2;
        const __half* ag = Ag + s * 64;
        const __half* bg = Bg + s * 64;
        #pragma unroll
        for (int c = 0; c < 4; c++) {
            cp16(ad + c * 16, ag + c * 8);
            cp16(bd + c * 16, bg + c * 8);
        }
        CP_COMMIT();
    }

    for (int kt = 0; kt < nk; kt++) {
        CP_WAIT1();
        __syncthreads();
        if (kt + 2 < nk) {
            int s = (kt + 2) % G_STAGES;
            uint32_t ad = AsA + s * G_TILE * 2;
            uint32_t bd = BsA + s * G_TILE * 2;
            const __half* ag = Ag + (kt + 2) * 64;
            const __half* bg = Bg + (kt + 2) * 64;
            #pragma unroll
            for (int c = 0; c < 4; c++) {
                cp16(ad + c * 16, ag + c * 8);
                cp16(bd + c * 16, bg + c * 8);
            }
        }
        CP_COMMIT();

        const int buf = kt % G_STAGES;
        const uint32_t aB = asU + buf * G_TILE * 2 + aoff;
        const uint32_t bB = bsU + buf * G_TILE * 2 + boff;
        #pragma unroll
        for (int kk = 0; kk < 64; kk += 16) {
            uint32_t af[2][4], bf[4][4];
            #pragma unroll
            for (int i = 0; i < 2; i++)
                ldsm4(af[i], aB + kk * 2 + i * 16 * GS_STR * 2);
            #pragma unroll
            for (int jp = 0; jp < 4; jp++)
                ldsm4(bf[jp], bB + kk * 2 + jp * 16 * GS_STR * 2);
            #pragma unroll
            for (int i = 0; i < 2; i++)
                #pragma unroll
                for (int jp = 0; jp < 4; jp++) {
                    mma16(acc[i][2 * jp],     af[i], &bf[jp][0]);
                    mma16(acc[i][2 * jp + 1], af[i], &bf[jp][2]);
                }
        }
    }

    #pragma unroll
    for (int i = 0; i < 2; i++) {
        int row = m0 + wm + i * 16 + g;
        #pragma unroll
        for (int j = 0; j < 8; j++) {
            int col = n0 + wn + (j >> 1) * 16 + (j & 1) * 8 + 2 * q;
            float b0 = __ldg(&bias[col]), b1 = __ldg(&bias[col + 1]);
            float v0 = acc[i][j][0] + b0, v1 = acc[i][j][1] + b1;
            float v2 = acc[i][j][2] + b0, v3 = acc[i][j][3] + b1;
            if (ROUND) {
                __half* Ch = (__half*)Cv;
                float sc = (col < qcols) ? QSCALE : 1.0f;
                *(__half2*)(Ch + (size_t)row * N + col) =
                    __floats2half2_rn(v0 * sc, v1 * sc);
                *(__half2*)(Ch + (size_t)(row + 8) * N + col) =
                    __floats2half2_rn(v2 * sc, v3 * sc);
            } else {
                float* Cf = (float*)Cv;
                *(float2*)(Cf + (size_t)row * N + col) = make_float2(v0, v1);
                *(float2*)(Cf + (size_t)(row + 8) * N + col) = make_float2(v2, v3);
            }
        }
    }
}

// ------------------------------ attention ----------------------------------
// EXACT R13 version (428us known-pass): BQ=128, BKV=64, 8 warps;
// Q frags hoisted; P from S regs; ex2.approx.f16x2; l via ones-column of V.
#define AQ_STR 72          // halves per row (144B); V data cols 0..63, ones col 64
#define KV_TILE (64 * AQ_STR)
#define A_SMEM ((128 * AQ_STR + 4 * KV_TILE) * 2)

__global__ void __launch_bounds__(256, 2) attn_mma()
{
    extern __shared__ __half smh[];
    __half* Qs = smh;                 // [128][72] (pre-scaled by 0.125*log2e)
    const uint32_t qsU = smem_u32(Qs);
    const uint32_t kvU = qsU + 128 * AQ_STR * 2;   // [b][ K:64x72 | V:64x72 ]

    const int tid = threadIdx.x;
    const int lane = tid & 31, warp = tid >> 5;
    const int g = lane >> 2, q = lane & 3;
    const int qt = gridDim.x - 1 - blockIdx.x;   // heaviest tiles first
    const int q0 = qt * 128;
    const int h = blockIdx.y, b = blockIdx.z;

    const __half* base = g_qkv16 + (size_t)b * SEQ * QKV_STRIDE + h * HEAD_DIM;

    // ldmatrix lane source offsets
    const int a_r = (lane & 7) + ((lane >> 3) & 1) * 8;
    const int a_h = (lane >> 4) * 8;
    const int b_n = (lane & 7) + ((lane >> 4) & 1) * 8;
    const int b_h = ((lane >> 3) & 1) * 8;
    const int v_r = (lane & 7) + ((lane >> 3) & 1) * 8;
    const int v_h = (lane >> 4) * 8;
    const uint32_t aoffQ = ((warp * 16 + a_r) * AQ_STR + a_h) * 2;
    const uint32_t boffK = (b_n * AQ_STR + b_h) * 2;
    const uint32_t ooffV = (((lane & 15)) * AQ_STR + 64) * 2;   // ones-col ldsm.x2

    // loader mapping for K/V tiles: 64 rows x 64 halves, 2 cp16/thread each
    const int krow = tid >> 2, kch = (tid & 3) * 16;
    const __half* kvsrc = base + (size_t)krow * QKV_STRIDE + kch;

    // init ones columns (cols 64..71) of both V buffers: {1,0,0,0,0,0,0,0}
    if (tid < 128) {
        int bufi = tid >> 6, row = tid & 63;
        __half* vrow = smh + 128 * AQ_STR + bufi * 2 * KV_TILE + KV_TILE + row * AQ_STR + 64;
        *(__half2*)(vrow)     = __floats2half2_rn(1.0f, 0.0f);
        *(__half2*)(vrow + 2) = __floats2half2_rn(0.0f, 0.0f);
        *(__half2*)(vrow + 4) = __floats2half2_rn(0.0f, 0.0f);
        *(__half2*)(vrow + 6) = __floats2half2_rn(0.0f, 0.0f);
    }

    // prologue: Q tile + kv0 K/V, single commit group
    #pragma unroll
    for (int jj = 0; jj < 4; jj++) {
        int idx = tid + 256 * jj;
        int row = idx >> 3, ch = (idx & 7) * 8;
        cp16(qsU + (row * AQ_STR + ch) * 2, base + (size_t)(q0 + row) * QKV_STRIDE + ch);
    }
    {
        uint32_t kd = kvU + (krow * AQ_STR + kch) * 2;
        cp16(kd, kvsrc + D_MODEL);     cp16(kd + 16, kvsrc + D_MODEL + 8);
        uint32_t vd = kd + KV_TILE * 2;
        cp16(vd, kvsrc + 2 * D_MODEL); cp16(vd + 16, kvsrc + 2 * D_MODEL + 8);
    }
    CP_COMMIT();
    CP_WAIT0();
    __syncthreads();

    // hoist Q fragments (loop-invariant)
    uint32_t qf[4][4];
    #pragma unroll
    for (int t = 0; t < 4; t++)
        ldsm4(qf[t], qsU + aoffQ + t * 32);

    float m0r[2] = {-1e30f, -1e30f};
    float O[8][4];
    float OL[4];
    #pragma unroll
    for (int j = 0; j < 8; j++)
        #pragma unroll
        for (int t = 0; t < 4; t++) O[j][t] = 0.0f;
    #pragma unroll
    for (int t = 0; t < 4; t++) OL[t] = 0.0f;

    const int ra = q0 + warp * 16 + g;
    const int rb = ra + 8;
    const int nkv = 2 * (qt + 1);

    for (int kv = 0; kv < nkv; kv++) {
        const int kv0 = kv * 64;
        // prefetch next kv tile (its buffer was released by last iter's barrier)
        if (kv + 1 < nkv) {
            uint32_t bufn = ((kv + 1) & 1) * 2 * KV_TILE * 2;
            const __half* src = kvsrc + (size_t)(kv0 + 64) * QKV_STRIDE;
            uint32_t kd = kvU + bufn + (krow * AQ_STR + kch) * 2;
            cp16(kd, src + D_MODEL);     cp16(kd + 16, src + D_MODEL + 8);
            uint32_t vd = kd + KV_TILE * 2;
            cp16(vd, src + 2 * D_MODEL); cp16(vd + 16, src + 2 * D_MODEL + 8);
        }
        CP_COMMIT();

        const uint32_t kB = kvU + (kv & 1) * 2 * KV_TILE * 2;
        const uint32_t vB = kB + KV_TILE * 2;

        // S = Q K^T  (m16 x n64 per warp, k=64)
        float sacc[8][4];
        #pragma unroll
        for (int j = 0; j < 8; j++)
            #pragma unroll
            for (int t = 0; t < 4; t++) sacc[j][t] = 0.0f;
        #pragma unroll
        for (int t = 0; t < 4; t++) {
            uint32_t bf[4][4];
            #pragma unroll
            for (int jp = 0; jp < 4; jp++)
                ldsm4(bf[jp], kB + boffK + t * 32 + jp * 16 * AQ_STR * 2);
            #pragma unroll
            for (int jp = 0; jp < 4; jp++) {
                mma16(sacc[2 * jp],     qf[t], &bf[jp][0]);
                mma16(sacc[2 * jp + 1], qf[t], &bf[jp][2]);
            }
        }

        // causal mask (diagonal reachable only in last two kv tiles)
        if (kv >= nkv - 2) {
            #pragma unroll
            for (int j = 0; j < 8; j++) {
                int c0 = kv0 + (j >> 1) * 16 + (j & 1) * 8 + 2 * q;
                if (c0 > ra)     sacc[j][0] = -1e30f;
                if (c0 + 1 > ra) sacc[j][1] = -1e30f;
                if (c0 > rb)     sacc[j][2] = -1e30f;
                if (c0 + 1 > rb) sacc[j][3] = -1e30f;
            }
        }

        // row max (log2 domain)
        float mxa = -1e30f, mxb = -1e30f;
        #pragma unroll
        for (int j = 0; j < 8; j++) {
            mxa = fmaxf(mxa, fmaxf(sacc[j][0], sacc[j][1]));
            mxb = fmaxf(mxb, fmaxf(sacc[j][2], sacc[j][3]));
        }
        mxa = fmaxf(mxa, __shfl_xor_sync(0xffffffff, mxa, 1));
        mxa = fmaxf(mxa, __shfl_xor_sync(0xffffffff, mxa, 2));
        mxb = fmaxf(mxb, __shfl_xor_sync(0xffffffff, mxb, 1));
        mxb = fmaxf(mxb, __shfl_xor_sync(0xffffffff, mxb, 2));

        float mna = fmaxf(m0r[0], mxa), mnb = fmaxf(m0r[1], mxb);
        float aa = exp2f(m0r[0] - mna), ab = exp2f(m0r[1] - mnb);
        m0r[0] = mna; m0r[1] = mnb;

        // P = ex2(S - m) computed in f16x2 (C-frag layout == A-frag layout)
        uint32_t pl[8], ph[8];
        #pragma unroll
        for (int j = 0; j < 8; j++) {
            pl[j] = ex2_h2(h2u(__floats2half2_rn(sacc[j][0] - mna, sacc[j][1] - mna)));
            ph[j] = ex2_h2(h2u(__floats2half2_rn(sacc[j][2] - mnb, sacc[j][3] - mnb)));
        }
        // rescale O and l-accumulator
        #pragma unroll
        for (int j = 0; j < 8; j++) {
            O[j][0] *= aa; O[j][1] *= aa;
            O[j][2] *= ab; O[j][3] *= ab;
        }
        OL[0] *= aa; OL[1] *= aa; OL[2] *= ab; OL[3] *= ab;

        // O += P @ V ; l-col via ones column (n8 tile at col 64)
        #pragma unroll
        for (int t = 0; t < 4; t++) {
            uint32_t af[4] = {pl[2 * t], ph[2 * t], pl[2 * t + 1], ph[2 * t + 1]};
            uint32_t bf[4][4];
            #pragma unroll
            for (int jp = 0; jp < 4; jp++)
                ldsm4t(bf[jp], vB + ((16 * t + v_r) * AQ_STR + jp * 16 + v_h) * 2);
            uint32_t bo[2];
            ldsm2t(bo, vB + 16 * t * AQ_STR * 2 + ooffV);
            #pragma unroll
            for (int jp = 0; jp < 4; jp++) {
                mma16(O[2 * jp],     af, &bf[jp][0]);
                mma16(O[2 * jp + 1], af, &bf[jp][2]);
            }
            mma16(OL, af, bo);
        }

        CP_WAIT0();
        __syncthreads();
    }

    // epilogue: l lives in q=0 lanes' OL[0]/OL[2] (col 64); broadcast in quad
    float la = __shfl_sync(0xffffffff, OL[0], lane & ~3);
    float lb = __shfl_sync(0xffffffff, OL[2], lane & ~3);
    float inva = 1.0f / la, invb = 1.0f / lb;
    __half* outa = g_attn16 + ((size_t)b * SEQ + ra) * D_MODEL + h * HEAD_DIM;
    __half* outb = g_attn16 + ((size_t)b * SEQ + rb) * D_MODEL + h * HEAD_DIM;
    #pragma unroll
    for (int j = 0; j < 8; j++) {
        int c = (j >> 1) * 16 + (j & 1) * 8 + 2 * q;
        *(__half2*)(outa + c) = __floats2half2_rn(O[j][0] * inva, O[j][1] * inva);
        *(__half2*)(outb + c) = __floats2half2_rn(O[j][2] * invb, O[j][3] * invb);
    }
}

// ---------------------------------------------------------------------------
extern "C" void kernel_launch(void* const* d_in, const int* in_sizes, int n_in,
                              void* d_out, int out_size)
{
    (void)in_sizes; (void)n_in; (void)out_size;
    const float* x     = (const float*)d_in[0];
    const float* w_qkv = (const float*)d_in[1];
    const float* b_qkv = (const float*)d_in[2];
    const float* w_out = (const float*)d_in[3];
    const float* b_out = (const float*)d_in[4];
    float* out = (float*)d_out;

    __half *x16, *qkv16, *attn16, *wqkvT16, *woT16;
    cudaGetSymbolAddress((void**)&x16, g_x16);
    cudaGetSymbolAddress((void**)&qkv16, g_qkv16);
    cudaGetSymbolAddress((void**)&attn16, g_attn16);
    cudaGetSymbolAddress((void**)&wqkvT16, g_wqkvT16);
    cudaGetSymbolAddress((void**)&woT16, g_woT16);

    cudaFuncSetAttribute(gemm_mma<true>,  cudaFuncAttributeMaxDynamicSharedMemorySize, G_SMEM);
    cudaFuncSetAttribute(gemm_mma<false>, cudaFuncAttributeMaxDynamicSharedMemorySize, G_SMEM);
    cudaFuncSetAttribute(attn_mma, cudaFuncAttributeMaxDynamicSharedMemorySize, A_SMEM);

    const int M = BATCH * SEQ;  // 8192

    convert_x<<<(M * D_MODEL) / (256 * 4), 256>>>(x, x16);
    transpose_w<<<dim3(3 * D_MODEL / 32, D_MODEL / 32), dim3(32, 8)>>>(w_qkv, wqkvT16, D_MODEL, 3 * D_MODEL);
    transpose_w<<<dim3(D_MODEL / 32, D_MODEL / 32), dim3(32, 8)>>>(w_out, woT16, D_MODEL, D_MODEL);

    // 1) QKV projection (fp16 out, q cols pre-scaled by 0.125*log2e)
    gemm_mma<true><<<dim3(3 * D_MODEL / 128, M / 128), 256, G_SMEM>>>(
        x16, wqkvT16, b_qkv, qkv16, M, 3 * D_MODEL, D_MODEL, D_MODEL);

    // 2) causal flash attention (fp16 in/out)
    attn_mma<<<dim3(SEQ / 128, N_HEADS, BATCH), 256, A_SMEM>>>();

    // 3) output projection (fp32 out)
    gemm_mma<false><<<dim3(D_MODEL / 128, M / 128), 256, G_SMEM>>>(
        attn16, woT16, b_out, out, M, D_MODEL, D_MODEL, 0);
}